// round 15
// baseline (speedup 1.0000x reference)
#include <cuda_runtime.h>
#include <cstdint>
#include <cub/cub.cuh>

#define NUM_A 9
#define HH 128
#define WW 128
#define NBOX (NUM_A * HH * WW)   /* 147456 */
#define KTOP 6000
#define NPOST 300
#define NMS_NT 1024
#define OWN 7                    /* warps 1..31: 992*7 = 6944 >= 6000 */
#define NWORDS 188               /* ceil(6000/32) */
#define WIN 32
#define FULLM 0xFFFFFFFFu

__constant__ float c_sizes[NUM_A] = {4.f, 8.f, 12.f, 16.f, 24.f, 32.f, 48.f, 64.f, 96.f};

__device__ unsigned g_sk_a[NBOX], g_sk_b[NBOX], g_sv_a[NBOX], g_sv_b[NBOX];
__device__ unsigned g_yk_a[KTOP], g_yk_b[KTOP], g_yv_a[KTOP], g_yv_b[KTOP];
__device__ float4 g_props[KTOP];
__device__ __align__(256) unsigned char g_cub_temp[32u * 1024u * 1024u];

// ---------------- decode (bit-exact vs reference) ----------------
__device__ __forceinline__ float4 decode_box(int idx, const float4* __restrict__ deltas,
                                             bool* keep)
{
    int a   = idx / (HH * WW);
    int rem = idx - a * (HH * WW);
    int h   = rem >> 7;
    int w   = rem & 127;
    float s    = c_sizes[a];
    float half = s * 0.5f;
    float ax = ((float)h + 0.5f) - half;
    float ay = ((float)w + 0.5f) - half;
    float4 d = deltas[idx];
    float x1 = fmaxf(ax + d.x, 0.0f);
    float y1 = fmaxf(ay + d.y, 0.0f);
    float bw = fmaxf(s + d.z, 0.0f);
    float bh = fmaxf(s + d.w, 0.0f);
    float x2 = x1 + bw;
    float y2 = y1 + bh;
    x1 = fminf(x1, 128.0f);
    y1 = fminf(y1, 128.0f);
    x2 = fminf(x2, 128.0f);
    y2 = fminf(y2, 128.0f);
    float ow = x2 - x1;
    float oh = y2 - y1;
    *keep = (ow >= 3.0f) && (oh >= 3.0f);
    return make_float4(x1, y1, ow, oh);
}

// exact: rn(n/ar) >= 0.7f, division-free common path
__device__ __forceinline__ bool iou_ge(float n, float ar)
{
    float t = fmaf(-0.7f, ar, n);
    if (t >= 0.0f) return true;
    if (t <= -3.2e-8f * ar) return false;
    return __fdiv_rn(n, ar) >= 0.7f;
}

__global__ void k_score(const float* __restrict__ scores, const float4* __restrict__ deltas)
{
    int i = blockIdx.x * blockDim.x + threadIdx.x;
    if (i >= NBOX) return;
    bool keep;
    (void)decode_box(i, deltas, &keep);
    float sc = keep ? scores[i] : __int_as_float(0xFF800000);
    unsigned u   = __float_as_uint(sc);
    unsigned asc = u ^ ((unsigned)((int)u >> 31) | 0x80000000u);
    g_sk_a[i] = ~asc;
    g_sv_a[i] = (unsigned)i;
}

__global__ void k_props(const float4* __restrict__ deltas)
{
    int r = blockIdx.x * blockDim.x + threadIdx.x;
    if (r >= KTOP) return;
    int idx = (int)g_sv_b[r];
    bool keep;
    float4 p = decode_box(idx, deltas, &keep);
    g_props[r] = p;
    float y2 = p.y + p.w;
    g_yk_a[r] = ~__float_as_uint(y2);
    g_yv_a[r] = (unsigned)r;
}

// ---------------- NMS ----------------
struct SmemNMS {
    float4   sbox[KTOP];          // (x1,y1,x2,y2) y2-desc sorted
    unsigned swords[NWORDS];      // validity bitmask (monotone decreasing)
    int      T[132];              // T[k] = first m with y2[m] <= k
    int      s_nc[2];
    int      scidx[2][WIN];
    float4   scbox[2][WIN];
    int      sJ1c[2][WIN];
    unsigned srow[WIN];
    int      ssc[NMS_NT];
};

__global__ void __launch_bounds__(NMS_NT, 1) k_nms(float* __restrict__ out)
{
    extern __shared__ char sm_raw[];
    SmemNMS* s = (SmemNMS*)sm_raw;

    const int tid  = threadIdx.x;
    const int lane = tid & 31;
    const int wid  = tid >> 5;

    for (int i = tid; i < NPOST * 4; i += NMS_NT) out[i] = 0.0f;

    // boxes in y2-sorted order
    for (int m = tid; m < KTOP; m += NMS_NT) {
        float4 p = g_props[(int)g_yv_b[m]];
        s->sbox[m] = make_float4(p.x, p.y, p.x + p.z, p.y + p.w);
    }
    if (tid < NWORDS) s->swords[tid] = (tid == NWORDS - 1) ? 0x0000FFFFu : FULLM;
    __syncthreads();

    // T table (first index with y2 <= k; y2 in [0,130))
    if (tid < 132) {
        float v = (float)tid;
        int lo = 0, hi = KTOP;
        while (lo < hi) { int mid = (lo + hi) >> 1; if (s->sbox[mid].w > v) lo = mid + 1; else hi = mid; }
        s->T[tid] = lo;
    }

    // owned boxes in registers (warps 1..31 only; warp 0 = gatherer)
    const int base = (wid >= 1) ? (tid - 32) * OWN : KTOP;
    float rx1[OWN], ry1[OWN], rx2[OWN], ry2[OWN], rar[OWN];
    unsigned rv = 0;
    float my_ymin1 = 1e30f;
#pragma unroll
    for (int q = 0; q < OWN; ++q) {
        int j = base + q;
        if (j < KTOP) {
            float4 b = s->sbox[j];
            rx1[q] = b.x; ry1[q] = b.y; rx2[q] = b.z; ry2[q] = b.w;
            rar[q] = fmaxf((b.z - b.x) * (b.w - b.y), 1e-6f);
            rv |= 1u << q;
            my_ymin1 = fminf(my_ymin1, b.y);
        } else {
            rx1[q] = 0.f; ry1[q] = 0.f; rx2[q] = 0.f; ry2[q] = 0.f; rar[q] = 1.f;
        }
    }
    float wmin_y1 = my_ymin1;
#pragma unroll
    for (int o = 16; o; o >>= 1) wmin_y1 = fminf(wmin_y1, __shfl_xor_sync(FULLM, wmin_y1, o));
    const int warp_first_box = (wid >= 1) ? (wid - 1) * 32 * OWN : 0;
    __syncthreads();

    int p = 0;  // gather cursor (warp 0 register, uniform within warp)

    // gather(buf): warp 0 only. May race with concurrent swords clears —
    // safe because bits are monotone decreasing; stale-1 candidates are
    // filtered by the post-barrier validity ballot at their turn.
    auto gather = [&](int buf) {
        int nc = 0;
        while (nc < WIN && p < KTOP) {
            int w0 = p >> 5;
            int widx = w0 + lane;
            unsigned w = (widx < NWORDS) ? s->swords[widx] : 0u;
            if (lane == 0) w &= (FULLM << (p & 31));
            int cnt = __popc(w);
            int pre = cnt;
#pragma unroll
            for (int o = 1; o < 32; o <<= 1) {
                int v = __shfl_up_sync(FULLM, pre, o);
                if (lane >= o) pre += v;
            }
            int total = __shfl_sync(FULLM, pre, 31);
            int r = nc + (pre - cnt);
            unsigned ww = w;
            while (ww && r < WIN) {
                int b = __ffs(ww) - 1; ww &= ww - 1;
                s->scidx[buf][r] = (widx << 5) + b;
                ++r;
            }
            nc += total; if (nc > WIN) nc = WIN;
            p = (w0 + 32) << 5;
            if (p > KTOP) p = KTOP;
            __syncwarp();
            if (nc == WIN) p = s->scidx[buf][WIN - 1] + 1;
        }
        if (lane < nc) {
            int c = s->scidx[buf][lane];
            float4 b = s->sbox[c];
            s->scbox[buf][lane] = b;
            float thr = b.y - 1.001f;
            int j1;
            if (thr < 0.0f) j1 = KTOP;
            else { int kk = (int)thr; if (kk > 131) kk = 131; j1 = s->T[kk]; }
            s->sJ1c[buf][lane] = j1;
        } else {
            s->scbox[buf][lane] = make_float4(1e30f, 1e30f, -1e30f, -1e30f);
            s->sJ1c[buf][lane] = 0;
            s->scidx[buf][lane] = 0;
        }
        if (lane == 0) s->s_nc[buf] = nc;
    };

    // prologue
    if (wid == 0) gather(0);
    __syncthreads();                                  // A

    int cur = 0;
    for (;;) {
        int nc = s->s_nc[cur];
        if (nc == 0) break;

        // ---- step 1 (all warps, parallel): validity ballot + row + prune ballots ----
        int cidx = s->scidx[cur][lane];
        int okv = 0;
        if (lane < nc) okv = (int)((s->swords[cidx >> 5] >> (cidx & 31)) & 1u);
        unsigned vm = __ballot_sync(FULLM, okv);

        {   // row `wid`: does candidate wid forward-suppress candidate lane?
            float4 cw = s->scbox[cur][wid];
            float4 cj = s->scbox[cur][lane];
            int ok = 0;
            if (lane > wid && lane < nc && wid < nc) {
                float arj = fmaxf((cj.z - cj.x) * (cj.w - cj.y), 1e-6f);
                float iw = fminf(cw.z, cj.z) - fmaxf(cw.x, cj.x) + 1.0f;
                float ih = fminf(cw.w, cj.w) - fmaxf(cw.y, cj.y) + 1.0f;
                if (iw > 0.0f && ih > 0.0f && iou_ge(iw * ih, arj)) ok = 1;
            }
            unsigned rm = __ballot_sync(FULLM, ok);
            if (lane == 0) s->srow[wid] = rm;
        }
        float cy2l = s->scbox[cur][lane].w;
        int   j1l  = s->sJ1c[cur][lane];
        unsigned ymask = __ballot_sync(FULLM, cy2l + 1.0001f > wmin_y1);
        unsigned amask = __ballot_sync(FULLM, j1l > warp_first_box);
        __syncthreads();                              // C: rows published

        // ---- step 2: warp 0 gathers next window; warps 1..31 chain+apply ----
        int nxt = cur ^ 1;
        if (wid == 0) {
            gather(nxt);
        } else {
            // warp-uniform guard: all 32 lanes participate in ballots/shfls
            unsigned whas = __ballot_sync(FULLM, rv != 0u);
            if (whas) {
                unsigned row = s->srow[lane];
                unsigned exec;
                if (__ballot_sync(FULLM, row != 0u) == 0u) {
                    exec = vm;
                } else {
                    unsigned rem = 0; exec = 0;
#pragma unroll
                    for (int l = 0; l < 32; ++l) {
                        unsigned rl = __shfl_sync(FULLM, row, l);
                        unsigned b = 1u << l;
                        if ((vm & b) && !(rem & b)) { exec |= b; rem |= rl; }
                    }
                }
                if (rv) {                             // sync-free below
                    unsigned oldrv = rv;
                    unsigned e = exec & ymask & amask;
                    while (e) {
                        int m = __ffs(e) - 1; e &= e - 1;
                        int qlim = s->sJ1c[cur][m] - base; if (qlim > OWN) qlim = OWN;
                        if (qlim <= 0) continue;
                        float4 cb = s->scbox[cur][m];
                        if (cb.w + 1.0001f <= my_ymin1) continue;
                        int ci = s->scidx[cur][m];
#pragma unroll
                        for (int q = 0; q < OWN; ++q) {
                            if (q < qlim && ((rv >> q) & 1u) && (base + q != ci)) {
                                float iw = fminf(cb.z, rx2[q]) - fmaxf(cb.x, rx1[q]) + 1.0f;
                                float ih = fminf(cb.w, ry2[q]) - fmaxf(cb.y, ry1[q]) + 1.0f;
                                if (iw > 0.0f && ih > 0.0f && iou_ge(iw * ih, rar[q]))
                                    rv &= ~(1u << q);
                            }
                        }
                    }
                    unsigned clr = oldrv & ~rv;
                    if (clr) {
                        unsigned long long m64 = (unsigned long long)clr << (base & 31);
                        int wdw = base >> 5;
                        unsigned lo = (unsigned)m64, hi = (unsigned)(m64 >> 32);
                        if (lo) atomicAnd(&s->swords[wdw], ~lo);
                        if (hi) atomicAnd(&s->swords[wdw + 1], ~hi);
                    }
                }
            }
        }
        __syncthreads();                              // A: applies + gather visible
        cur = nxt;
    }

    // ---- output: first NPOST survivors in index order ----
    int cnt = __popc(rv);
    s->ssc[tid] = cnt;
    __syncthreads();
    for (int off = 1; off < NMS_NT; off <<= 1) {
        int add = (tid >= off) ? s->ssc[tid - off] : 0;
        __syncthreads();
        s->ssc[tid] += add;
        __syncthreads();
    }
    int pos = s->ssc[tid] - cnt;
#pragma unroll
    for (int q = 0; q < OWN; ++q) {
        if ((rv >> q) & 1u) {
            if (pos < NPOST) {
                float4 pp = g_props[(int)g_yv_b[base + q]];
                out[pos * 4 + 0] = pp.x;
                out[pos * 4 + 1] = pp.y;
                out[pos * 4 + 2] = pp.z;
                out[pos * 4 + 3] = pp.w;
            }
            ++pos;
        }
    }
}

extern "C" void kernel_launch(void* const* d_in, const int* in_sizes, int n_in,
                              void* d_out, int out_size)
{
    const float*  scores = (const float*)d_in[0];
    const float4* deltas = (const float4*)d_in[1];
    float* out = (float*)d_out;
    (void)in_sizes; (void)n_in; (void)out_size;

    void *p_ska, *p_skb, *p_sva, *p_svb, *p_yka, *p_ykb, *p_yva, *p_yvb, *p_tmp;
    cudaGetSymbolAddress(&p_ska, g_sk_a);
    cudaGetSymbolAddress(&p_skb, g_sk_b);
    cudaGetSymbolAddress(&p_sva, g_sv_a);
    cudaGetSymbolAddress(&p_svb, g_sv_b);
    cudaGetSymbolAddress(&p_yka, g_yk_a);
    cudaGetSymbolAddress(&p_ykb, g_yk_b);
    cudaGetSymbolAddress(&p_yva, g_yv_a);
    cudaGetSymbolAddress(&p_yvb, g_yv_b);
    cudaGetSymbolAddress(&p_tmp, g_cub_temp);

    k_score<<<(NBOX + 255) / 256, 256>>>(scores, deltas);

    size_t tb = sizeof(g_cub_temp);
    cub::DeviceRadixSort::SortPairs(p_tmp, tb,
        (const unsigned*)p_ska, (unsigned*)p_skb,
        (const unsigned*)p_sva, (unsigned*)p_svb, NBOX);

    k_props<<<(KTOP + 255) / 256, 256>>>(deltas);

    tb = sizeof(g_cub_temp);
    cub::DeviceRadixSort::SortPairs(p_tmp, tb,
        (const unsigned*)p_yka, (unsigned*)p_ykb,
        (const unsigned*)p_yva, (unsigned*)p_yvb, KTOP);

    size_t smem = sizeof(SmemNMS);
    cudaFuncSetAttribute(k_nms, cudaFuncAttributeMaxDynamicSharedMemorySize, (int)smem);
    k_nms<<<1, NMS_NT, smem>>>(out);
}